// round 12
// baseline (speedup 1.0000x reference)
#include <cuda_runtime.h>
#include <cuda_fp16.h>
#include <math.h>
#include <stdint.h>

#define B_  8
#define S_  1024
#define D_  1024
#define H_  16
#define A_  4
#define DK_ 128

// ---------------- scratch (static device allocations) ------------------------
__device__ float g_xmean[B_ * D_];
__device__ int   g_idx [B_ * A_];
__device__ float g_gate[B_ * A_];
__device__ __align__(16) __half g_xh [(size_t)B_ * S_ * D_];
__device__ __align__(16) __half g_Q  [(size_t)B_ * A_ * S_ * DK_];  // pre-scaled
__device__ __align__(16) __half g_K  [(size_t)B_ * A_ * S_ * DK_];
__device__ __align__(16) __half g_Vt [(size_t)B_ * A_ * DK_ * S_];  // [z][dk][s]
__device__ __align__(16) __half g_cat[(size_t)B_ * S_ * A_ * DK_];
__device__ __align__(16) __half g_WqT[(size_t)H_ * DK_ * D_];       // [h][n][k]
__device__ __align__(16) __half g_WkT[(size_t)H_ * DK_ * D_];
__device__ __align__(16) __half g_WvT[(size_t)H_ * DK_ * D_];
__device__ __align__(16) __half g_WoT[(size_t)D_ * (A_ * DK_)];

// ---------------- helpers -----------------------------------------------------
static __device__ __forceinline__ void mma16816(float* c, const uint32_t* a,
                                                const uint32_t* b) {
    asm volatile(
        "mma.sync.aligned.m16n8k16.row.col.f32.f16.f16.f32 "
        "{%0,%1,%2,%3}, {%4,%5,%6,%7}, {%8,%9}, {%0,%1,%2,%3};"
        : "+f"(c[0]), "+f"(c[1]), "+f"(c[2]), "+f"(c[3])
        : "r"(a[0]), "r"(a[1]), "r"(a[2]), "r"(a[3]), "r"(b[0]), "r"(b[1]));
}
static __device__ __forceinline__ uint32_t smem_u32(const void* p) {
    uint32_t a;
    asm("{ .reg .u64 t; cvta.to.shared.u64 t, %1; cvt.u32.u64 %0, t; }"
        : "=r"(a) : "l"(p));
    return a;
}
static __device__ __forceinline__ uint32_t h2pack(float a, float b) {
    __half2 h = __floats2half2_rn(a, b);
    return *(uint32_t*)&h;
}
#define LDSM4(r0, r1, r2, r3, a) \
    asm volatile("ldmatrix.sync.aligned.m8n8.x4.shared.b16 {%0,%1,%2,%3}, [%4];" \
        : "=r"(r0), "=r"(r1), "=r"(r2), "=r"(r3) : "r"(a))
#define CP16(dst, src) \
    asm volatile("cp.async.cg.shared.global [%0], [%1], 16;" :: "r"(dst), "l"(src))
#define CP_COMMIT() asm volatile("cp.async.commit_group;" ::: "memory")
#define CP_WAIT(n)  asm volatile("cp.async.wait_group %0;" :: "n"(n) : "memory")

// ---------------- 1) fused mean + fp16 copy of x ------------------------------
__global__ void mean_copy_kernel(const float* __restrict__ x) {
    int b = blockIdx.y;
    int d = blockIdx.x * 256 + threadIdx.x;
    const float* xp = x + (size_t)b * S_ * D_ + d;
    __half* hp = g_xh + (size_t)b * S_ * D_ + d;
    float s = 0.f;
    #pragma unroll 4
    for (int t = 0; t < S_; ++t) {
        float v = xp[(size_t)t * D_];
        s += v;
        hp[(size_t)t * D_] = __float2half_rn(v);
    }
    g_xmean[b * D_ + d] = s * (1.0f / (float)S_);
}

// ---------------- 2) router ---------------------------------------------------
__global__ void router_kernel(const float* __restrict__ Wr,
                              const float* __restrict__ br) {
    int b = blockIdx.x;
    __shared__ float red[128][H_];
    int tid = threadIdx.x;
    float acc[H_];
    #pragma unroll
    for (int h = 0; h < H_; ++h) acc[h] = 0.f;
    for (int d = tid; d < D_; d += 128) {
        float xv = g_xmean[b * D_ + d];
        #pragma unroll
        for (int h = 0; h < H_; ++h) acc[h] += xv * Wr[d * H_ + h];
    }
    #pragma unroll
    for (int h = 0; h < H_; ++h) red[tid][h] = acc[h];
    __syncthreads();
    if (tid == 0) {
        float logit[H_];
        for (int h = 0; h < H_; ++h) {
            float s = 0.f;
            for (int t = 0; t < 128; ++t) s += red[t][h];
            logit[h] = s + br[h];
        }
        float mx = logit[0];
        for (int h = 1; h < H_; ++h) mx = fmaxf(mx, logit[h]);
        float dist[H_], sum = 0.f;
        for (int h = 0; h < H_; ++h) { dist[h] = expf(logit[h] - mx); sum += dist[h]; }
        for (int h = 0; h < H_; ++h) dist[h] /= sum;
        bool used[H_];
        for (int h = 0; h < H_; ++h) used[h] = false;
        int idxs[A_]; float vals[A_];
        for (int a = 0; a < A_; ++a) {
            int best = -1; float bv = -1.f;
            for (int h = 0; h < H_; ++h)
                if (!used[h] && dist[h] > bv) { bv = dist[h]; best = h; }
            used[best] = true; idxs[a] = best; vals[a] = bv;
        }
        float denom = (float)(H_ - A_);
        float ev[A_];
        for (int a = 0; a < A_; ++a) { ev[a] = expf(vals[a]); denom += ev[a]; }
        for (int a = 0; a < A_; ++a) {
            g_idx [b * A_ + a] = idxs[a];
            g_gate[b * A_ + a] = ev[a] / denom;
        }
    }
}

// ---------------- weight transposes (emit fp16) -------------------------------
__global__ void transpose_heads(const float* __restrict__ Wq,
                                const float* __restrict__ Wk,
                                const float* __restrict__ Wv) {
    __shared__ float t[32][33];
    int zb = blockIdx.z;
    int mat = zb >> 4, h = zb & 15;
    const float* W = (mat == 0) ? Wq : (mat == 1) ? Wk : Wv;
    __half*      O = (mat == 0) ? g_WqT : (mat == 1) ? g_WkT : g_WvT;
    int k0 = blockIdx.x * 32, n0 = blockIdx.y * 32;
    int tx = threadIdx.x, ty = threadIdx.y;
    const float* Wh = W + (size_t)h * D_ * DK_;
    __half*      Oh = O + (size_t)h * DK_ * D_;
    #pragma unroll
    for (int i = 0; i < 4; ++i)
        t[ty + 8 * i][tx] = Wh[(size_t)(k0 + ty + 8 * i) * DK_ + n0 + tx];
    __syncthreads();
    #pragma unroll
    for (int i = 0; i < 4; ++i)
        Oh[(size_t)(n0 + ty + 8 * i) * D_ + k0 + tx] = __float2half_rn(t[tx][ty + 8 * i]);
}

__global__ void transpose_wo(const float* __restrict__ Wo) {
    __shared__ float t[32][33];
    int k0 = blockIdx.x * 32, n0 = blockIdx.y * 32;
    int tx = threadIdx.x, ty = threadIdx.y;
    #pragma unroll
    for (int i = 0; i < 4; ++i)
        t[ty + 8 * i][tx] = Wo[(size_t)(k0 + ty + 8 * i) * D_ + n0 + tx];
    __syncthreads();
    #pragma unroll
    for (int i = 0; i < 4; ++i)
        g_WoT[(size_t)(n0 + ty + 8 * i) * (A_ * DK_) + k0 + tx] =
            __float2half_rn(t[tx][ty + 8 * i]);
}

// == fp16 GEMM, 8 warps / 32x64 warp tiles, single-barrier double buffer ========
#define PITCH_H 72
#define GEMM_SMEM_BYTES (4 * 128 * PITCH_H * 2)   // 73728

// EPI: 0 plain fp32 (+bias), 1 Q ((acc+bias)*sc -> fp16),
//      2 V transposed (+bias -> fp16), 3 K (+bias -> fp16)
template<int EPI>
static __device__ __forceinline__ void gemm128_h(
    const __half* __restrict__ A, int lda,
    const __half* __restrict__ Bt, int ldb,
    const float* __restrict__ bias,
    void* __restrict__ Cv, int ldc, int K, float sc)
{
    extern __shared__ __half shh[];
    const uint32_t base = smem_u32(shh);
    const uint32_t bufA[2] = { base,                         base + 128 * PITCH_H * 2 };
    const uint32_t bufB[2] = { base + 2 * 128 * PITCH_H * 2, base + 3 * 128 * PITCH_H * 2 };

    const int tid  = threadIdx.x;          // 256 threads
    const int lane = tid & 31;
    const int wid  = tid >> 5;
    const int wm   = wid & 3;
    const int wn   = wid >> 2;
    const int g    = lane >> 2;
    const int tig  = lane & 3;

    const int row = tid >> 1;
    const int hh  = (tid & 1);
    const __half* Ap = A  + (size_t)row * lda + hh * 32;
    const __half* Bp = Bt + (size_t)row * ldb + hh * 32;
    uint32_t sA[2], sB[2];
    sA[0] = bufA[0] + row * (PITCH_H * 2) + hh * 64;
    sA[1] = bufA[1] + row * (PITCH_H * 2) + hh * 64;
    sB[0] = bufB[0] + row * (PITCH_H * 2) + hh * 64;
    sB[1] = bufB[1] + row * (PITCH_H * 2) + hh * 64;

    const int arow = lane & 15;
    const int aco  = (lane >> 4) * 16;
    const int brow = ((lane >> 4) & 1) * 8 + (lane & 7);
    const int bco  = ((lane >> 3) & 1) * 16;
    uint32_t aAddr[2][2], bAddr[2][4];
    #pragma unroll
    for (int buf = 0; buf < 2; ++buf) {
        #pragma unroll
        for (int mi = 0; mi < 2; ++mi)
            aAddr[buf][mi] = bufA[buf] + (wm * 32 + mi * 16 + arow) * (PITCH_H * 2) + aco;
        #pragma unroll
        for (int p = 0; p < 4; ++p)
            bAddr[buf][p] = bufB[buf] + (wn * 64 + p * 16 + brow) * (PITCH_H * 2) + bco;
    }

    const int KIT = K >> 6;

    // prologue: stage 0
    #pragma unroll
    for (int j = 0; j < 4; ++j) {
        CP16(sA[0] + j * 16, Ap + j * 8);
        CP16(sB[0] + j * 16, Bp + j * 8);
    }
    CP_COMMIT();

    float acc[2][8][4];
    #pragma unroll
    for (int mi = 0; mi < 2; ++mi)
        #pragma unroll
        for (int ni = 0; ni < 8; ++ni)
            #pragma unroll
            for (int r = 0; r < 4; ++r) acc[mi][ni][r] = 0.f;

    for (int it = 0; it < KIT; ++it) {
        CP_WAIT(0);            // stage it resident
        __syncthreads();       // all warps done with iter it-1 (frees buf (it+1)&1)
        if (it + 1 < KIT) {    // prefetch stage it+1 under compute of stage it
            const __half* An = Ap + (size_t)(it + 1) * 64;
            const __half* Bn = Bp + (size_t)(it + 1) * 64;
            int nb = (it + 1) & 1;
            #pragma unroll
            for (int j = 0; j < 4; ++j) {
                CP16(sA[nb] + j * 16, An + j * 8);
                CP16(sB[nb] + j * 16, Bn + j * 8);
            }
            CP_COMMIT();
        }

        const int buf = it & 1;
        #pragma unroll
        for (int ks = 0; ks < 4; ++ks) {
            uint32_t a0[4], a1[4];
            LDSM4(a0[0], a0[1], a0[2], a0[3], aAddr[buf][0] + ks * 32);
            LDSM4(a1[0], a1[1], a1[2], a1[3], aAddr[buf][1] + ks * 32);
            #pragma unroll
            for (int p = 0; p < 4; ++p) {
                uint32_t bb[4];
                LDSM4(bb[0], bb[1], bb[2], bb[3], bAddr[buf][p] + ks * 32);
                mma16816(acc[0][2 * p],     a0, bb);
                mma16816(acc[1][2 * p],     a1, bb);
                mma16816(acc[0][2 * p + 1], a0, bb + 2);
                mma16816(acc[1][2 * p + 1], a1, bb + 2);
            }
        }
    }

    #pragma unroll
    for (int mi = 0; mi < 2; ++mi) {
        int r0 = wm * 32 + mi * 16 + g;
        #pragma unroll
        for (int ni = 0; ni < 8; ++ni) {
            int c = wn * 64 + ni * 8 + 2 * tig;
            float b0 = __ldg(bias + c), b1 = __ldg(bias + c + 1);
            float v0 = acc[mi][ni][0] + b0, v1 = acc[mi][ni][1] + b1;
            float v2 = acc[mi][ni][2] + b0, v3 = acc[mi][ni][3] + b1;
            if (EPI == 0) {
                float* C = (float*)Cv;
                *(float2*)&C[(size_t)r0 * ldc + c]       = make_float2(v0, v1);
                *(float2*)&C[(size_t)(r0 + 8) * ldc + c] = make_float2(v2, v3);
            } else if (EPI == 1) {
                __half* C = (__half*)Cv;
                *(__half2*)&C[(size_t)r0 * ldc + c]       = __floats2half2_rn(v0 * sc, v1 * sc);
                *(__half2*)&C[(size_t)(r0 + 8) * ldc + c] = __floats2half2_rn(v2 * sc, v3 * sc);
            } else if (EPI == 2) {
                __half* C = (__half*)Cv;
                C[(size_t)c * ldc + r0]           = __float2half_rn(v0);
                C[(size_t)(c + 1) * ldc + r0]     = __float2half_rn(v1);
                C[(size_t)c * ldc + r0 + 8]       = __float2half_rn(v2);
                C[(size_t)(c + 1) * ldc + r0 + 8] = __float2half_rn(v3);
            } else {
                __half* C = (__half*)Cv;
                *(__half2*)&C[(size_t)r0 * ldc + c]       = __floats2half2_rn(v0, v1);
                *(__half2*)&C[(size_t)(r0 + 8) * ldc + c] = __floats2half2_rn(v2, v3);
            }
        }
    }
}

// ---------------- 3) gathered QKV projections ---------------------------------
__global__ void __launch_bounds__(256, 2) qkv_tc(const float* __restrict__ bq,
                                                 const float* __restrict__ bk,
                                                 const float* __restrict__ bv) {
    int z = blockIdx.z;
    int b = z >> 2;
    int h = g_idx[z];
    const __half* Atile = g_xh + (size_t)b * S_ * D_ + (size_t)blockIdx.x * 128 * D_;
    const float sc = 0.08838834764831845f;
    if (blockIdx.y == 0) {
        __half* C = g_Q + (size_t)z * S_ * DK_ + (size_t)blockIdx.x * 128 * DK_;
        gemm128_h<1>(Atile, D_, g_WqT + (size_t)h * DK_ * D_, D_,
                     bq + h * DK_, C, DK_, D_, sc);
    } else if (blockIdx.y == 1) {
        __half* C = g_K + (size_t)z * S_ * DK_ + (size_t)blockIdx.x * 128 * DK_;
        gemm128_h<3>(Atile, D_, g_WkT + (size_t)h * DK_ * D_, D_,
                     bk + h * DK_, C, DK_, D_, 1.f);
    } else {
        __half* C = g_Vt + (size_t)z * DK_ * S_ + blockIdx.x * 128;
        gemm128_h<2>(Atile, D_, g_WvT + (size_t)h * DK_ * D_, D_,
                     bv + h * DK_, C, S_, D_, 1.f);
    }
}

// ---------------- 4) fp16 flash attention (reg-P, hoisted Q, dbl-buf K+V) -----
// smem halves: Q[128*136]@0, K0@17408, K1@26112, V0[128*72]@34816, V1@44032
#define FL_Q   0
#define FL_K0  17408
#define FL_K1  26112
#define FL_V0  34816
#define FL_V1  44032
#define FL_SMEM_BYTES ((44032 + 128 * 72) * 2)   // 106496

__global__ void __launch_bounds__(256, 1) flash_tc() {
    extern __shared__ __half fsh[];
    const int z = blockIdx.y, b = z >> 2, a = z & 3;
    const __half* Qg = g_Q + (size_t)z * S_ * DK_;
    const __half* Kg = g_K + (size_t)z * S_ * DK_;
    const __half* Vg = g_Vt + (size_t)z * DK_ * S_;
    const int tid = threadIdx.x, lane = tid & 31, w = tid >> 5;
    const int g = lane >> 2, tig = lane & 3;
    const int m0 = w * 16;
    const int qrow0 = blockIdx.x * 128;
    const uint32_t fsb = smem_u32(fsh);

    // cp.async mappings (double-buffered K and V)
    const int krow = tid >> 2;
    uint32_t sK[2];
    sK[0] = fsb + (FL_K0 + krow * 136) * 2 + (tid & 3) * 64;
    sK[1] = fsb + (FL_K1 + krow * 136) * 2 + (tid & 3) * 64;
    const __half* Kp = Kg + (size_t)krow * DK_ + (tid & 3) * 32;
    const int vrow = tid >> 1;
    uint32_t sV[2];
    sV[0] = fsb + (FL_V0 + vrow * 72) * 2 + (tid & 1) * 64;
    sV[1] = fsb + (FL_V1 + vrow * 72) * 2 + (tid & 1) * 64;
    const __half* Vp = Vg + (size_t)vrow * S_ + (tid & 1) * 32;

    // ldmatrix lane addressing
    const int arow = lane & 15;
    const int aco  = (lane >> 4) * 16;
    const int brow = ((lane >> 4) & 1) * 8 + (lane & 7);
    const int bco  = ((lane >> 3) & 1) * 16;
    const uint32_t qAddr = fsb + (FL_Q + (m0 + arow) * 136) * 2 + aco;
    uint32_t kAddr[2][4], vAddr[2][8];
    #pragma unroll
    for (int p = 0; p < 4; ++p) {
        kAddr[0][p] = fsb + (FL_K0 + (p * 16 + brow) * 136) * 2 + bco;
        kAddr[1][p] = fsb + (FL_K1 + (p * 16 + brow) * 136) * 2 + bco;
    }
    #pragma unroll
    for (int p = 0; p < 8; ++p) {
        vAddr[0][p] = fsb + (FL_V0 + (p * 16 + brow) * 72) * 2 + bco;
        vAddr[1][p] = fsb + (FL_V1 + (p * 16 + brow) * 72) * 2 + bco;
    }

    // prologue: K(0) + V(0) as one group
    #pragma unroll
    for (int j = 0; j < 4; ++j) CP16(sK[0] + j * 16, Kp + j * 8);
    #pragma unroll
    for (int j = 0; j < 4; ++j) CP16(sV[0] + j * 16, Vp + j * 8);
    CP_COMMIT();

    // Q fill
    #pragma unroll
    for (int l = 0; l < 8; ++l) {
        int chunk = tid + l * 256;
        int r = chunk >> 4, c = (chunk & 15) * 8;
        *(uint4*)&fsh[FL_Q + r * 136 + c] =
            *(const uint4*)(Qg + (size_t)(qrow0 + r) * DK_ + c);
    }
    __syncthreads();

    // hoist Q fragments (loop-invariant)
    uint32_t qf[8][4];
    #pragma unroll
    for (int ks = 0; ks < 8; ++ks)
        LDSM4(qf[ks][0], qf[ks][1], qf[ks][2], qf[ks][3], qAddr + ks * 32);

    float o[16][4];
    #pragma unroll
    for (int ni = 0; ni < 16; ++ni)
        #pragma unroll
        for (int r = 0; r < 4; ++r) o[ni][r] = 0.f;
    float mr0 = -1e30f, mr1 = -1e30f, l0 = 0.f, l1 = 0.f;

    for (int kt = 0; kt < S_ / 64; ++kt) {
        CP_WAIT(0);            // K(kt), V(kt) resident
        __syncthreads();       // all warps finished iter kt-1 (frees buf (kt+1)&1)
        if (kt + 1 < S_ / 64) {
            const __half* Kn = Kp + (size_t)(kt + 1) * 64 * DK_;
            const __half* Vn = Vp + (size_t)(kt + 1) * 64;
            const int nb = (kt + 1) & 1;
            #pragma unroll
            for (int j = 0; j < 4; ++j) CP16(sK[nb] + j * 16, Kn + j * 8);
            #pragma unroll
            for (int j = 0; j < 4; ++j) CP16(sV[nb] + j * 16, Vn + j * 8);
            CP_COMMIT();
        }

        // ---- S = Q K^T ----
        const int kb = kt & 1;
        float sacc[8][4];
        #pragma unroll
        for (int ni = 0; ni < 8; ++ni)
            #pragma unroll
            for (int r = 0; r < 4; ++r) sacc[ni][r] = 0.f;

        #pragma unroll
        for (int ks = 0; ks < 8; ++ks) {
            #pragma unroll
            for (int p = 0; p < 4; ++p) {
                uint32_t bb[4];
                LDSM4(bb[0], bb[1], bb[2], bb[3], kAddr[kb][p] + ks * 32);
                mma16816(sacc[2 * p],     qf[ks], bb);
                mma16816(sacc[2 * p + 1], qf[ks], bb + 2);
            }
        }

        // ---- online softmax ----
        float mt0 = -1e30f, mt1 = -1e30f;
        #pragma unroll
        for (int ni = 0; ni < 8; ++ni) {
            mt0 = fmaxf(mt0, fmaxf(sacc[ni][0], sacc[ni][1]));
            mt1 = fmaxf(mt1, fmaxf(sacc[ni][2], sacc[ni][3]));
        }
        mt0 = fmaxf(mt0, __shfl_xor_sync(0xffffffffu, mt0, 1));
        mt0 = fmaxf(mt0, __shfl_xor_sync(0xffffffffu, mt0, 2));
        mt1 = fmaxf(mt1, __shfl_xor_sync(0xffffffffu, mt1, 1));
        mt1 = fmaxf(mt1, __shfl_xor_sync(0xffffffffu, mt1, 2));

        // warp-uniform guard: rescale only if some row's max actually moved
        unsigned needv = __ballot_sync(0xffffffffu, (mt0 > mr0) || (mt1 > mr1));

        float mn0 = fmaxf(mr0, mt0), mn1 = fmaxf(mr1, mt1);
        float al0 = __expf(mr0 - mn0), al1 = __expf(mr1 - mn1);
        float ls0 = 0.f, ls1 = 0.f;
        #pragma unroll
        for (int ni = 0; ni < 8; ++ni) {
            sacc[ni][0] = __expf(sacc[ni][0] - mn0);
            sacc[ni][1] = __expf(sacc[ni][1] - mn0);
            sacc[ni][2] = __expf(sacc[ni][2] - mn1);
            sacc[ni][3] = __expf(sacc[ni][3] - mn1);
            ls0 += sacc[ni][0] + sacc[ni][1];
            ls1 += sacc[ni][2] + sacc[ni][3];
        }
        ls0 += __shfl_xor_sync(0xffffffffu, ls0, 1);
        ls0 += __shfl_xor_sync(0xffffffffu, ls0, 2);
        ls1 += __shfl_xor_sync(0xffffffffu, ls1, 1);
        ls1 += __shfl_xor_sync(0xffffffffu, ls1, 2);

        l0 = l0 * al0 + ls0;  mr0 = mn0;
        l1 = l1 * al1 + ls1;  mr1 = mn1;

        if (needv) {           // skip when all al == 1.0 exactly (bitwise identical)
            #pragma unroll
            for (int ni = 0; ni < 16; ++ni) {
                o[ni][0] *= al0; o[ni][1] *= al0;
                o[ni][2] *= al1; o[ni][3] *= al1;
            }
        }

        // ---- P: C-fragment -> A-fragment in registers ----
        uint32_t pf[4][4];
        #pragma unroll
        for (int ks = 0; ks < 4; ++ks) {
            pf[ks][0] = h2pack(sacc[2 * ks][0],     sacc[2 * ks][1]);
            pf[ks][1] = h2pack(sacc[2 * ks][2],     sacc[2 * ks][3]);
            pf[ks][2] = h2pack(sacc[2 * ks + 1][0], sacc[2 * ks + 1][1]);
            pf[ks][3] = h2pack(sacc[2 * ks + 1][2], sacc[2 * ks + 1][3]);
        }

        // ---- O += P V ----
        #pragma unroll
        for (int ks = 0; ks < 4; ++ks) {
            #pragma unroll
            for (int p = 0; p < 8; ++p) {
                uint32_t bb[4];
                LDSM4(bb[0], bb[1], bb[2], bb[3], vAddr[kb][p] + ks * 32);
                mma16816(o[2 * p],     pf[ks], bb);
                mma16816(o[2 * p + 1], pf[ks], bb + 2);
            }
        }
    }

    // ---- epilogue: normalize, gate, concat (fp16) ----
    float gate = g_gate[z];
    float inv0 = gate / l0, inv1 = gate / l1;
    int r0 = qrow0 + m0 + g, r1 = r0 + 8;
    __half* ob0 = g_cat + ((size_t)b * S_ + r0) * (A_ * DK_) + a * DK_;
    __half* ob1 = g_cat + ((size_t)b * S_ + r1) * (A_ * DK_) + a * DK_;
    #pragma unroll
    for (int ni = 0; ni < 16; ++ni) {
        int c = ni * 8 + 2 * tig;
        *(__half2*)&ob0[c] = __floats2half2_rn(o[ni][0] * inv0, o[ni][1] * inv0);
        *(__half2*)&ob1[c] = __floats2half2_rn(o[ni][2] * inv1, o[ni][3] * inv1);
    }
}

// ---------------- 5) output projection -----------------------------------------
__global__ void __launch_bounds__(256, 2) outproj_tc(const float* __restrict__ bo,
                                                     float* __restrict__ out) {
    const __half* Atile = g_cat + (size_t)blockIdx.x * 128 * (A_ * DK_);
    const __half* Bt = g_WoT + (size_t)blockIdx.y * 128 * (A_ * DK_);
    float* C = out + (size_t)blockIdx.x * 128 * D_ + blockIdx.y * 128;
    gemm128_h<0>(Atile, A_ * DK_, Bt, A_ * DK_, bo + blockIdx.y * 128,
                 C, D_, A_ * DK_, 1.f);
}

// ---------------- launch --------------------------------------------------------
extern "C" void kernel_launch(void* const* d_in, const int* in_sizes, int n_in,
                              void* d_out, int out_size) {
    const float* x  = (const float*)d_in[0];
    const float* Wq = (const float*)d_in[1];
    const float* bq = (const float*)d_in[2];
    const float* Wk = (const float*)d_in[3];
    const float* bk = (const float*)d_in[4];
    const float* Wv = (const float*)d_in[5];
    const float* bv = (const float*)d_in[6];
    const float* Wr = (const float*)d_in[7];
    const float* br = (const float*)d_in[8];
    const float* Wo = (const float*)d_in[9];
    const float* bo = (const float*)d_in[10];
    float* out = (float*)d_out;

    cudaFuncSetAttribute(flash_tc, cudaFuncAttributeMaxDynamicSharedMemorySize,
                         FL_SMEM_BYTES);
    cudaFuncSetAttribute(qkv_tc, cudaFuncAttributeMaxDynamicSharedMemorySize,
                         GEMM_SMEM_BYTES);
    cudaFuncSetAttribute(outproj_tc, cudaFuncAttributeMaxDynamicSharedMemorySize,
                         GEMM_SMEM_BYTES);

    mean_copy_kernel<<<dim3(D_ / 256, B_), 256>>>(x);
    router_kernel   <<<B_, 128>>>(Wr, br);
    transpose_heads <<<dim3(D_ / 32, DK_ / 32, 3 * H_), dim3(32, 8)>>>(Wq, Wk, Wv);
    transpose_wo    <<<dim3((A_ * DK_) / 32, D_ / 32), dim3(32, 8)>>>(Wo);
    qkv_tc          <<<dim3(S_ / 128, 3, B_ * A_), 256, GEMM_SMEM_BYTES>>>(bq, bk, bv);
    flash_tc        <<<dim3(S_ / 128, B_ * A_), 256, FL_SMEM_BYTES>>>();
    outproj_tc      <<<dim3((B_ * S_) / 128, D_ / 128), 256, GEMM_SMEM_BYTES>>>(bo, out);
}

// round 13
// speedup vs baseline: 1.0400x; 1.0400x over previous
#include <cuda_runtime.h>
#include <cuda_fp16.h>
#include <math.h>
#include <stdint.h>

#define B_  8
#define S_  1024
#define D_  1024
#define H_  16
#define A_  4
#define DK_ 128

// ---------------- scratch (static device allocations) ------------------------
__device__ float g_xmean[B_ * D_];
__device__ int   g_idx [B_ * A_];
__device__ float g_gate[B_ * A_];
__device__ __align__(16) __half g_xh [(size_t)B_ * S_ * D_];
__device__ __align__(16) __half g_Q  [(size_t)B_ * A_ * S_ * DK_];  // pre-scaled
__device__ __align__(16) __half g_K  [(size_t)B_ * A_ * S_ * DK_];
__device__ __align__(16) __half g_Vt [(size_t)B_ * A_ * DK_ * S_];  // [z][dk][s]
__device__ __align__(16) __half g_cat[(size_t)B_ * S_ * A_ * DK_];
__device__ __align__(16) __half g_WqT[(size_t)H_ * DK_ * D_];       // [h][n][k]
__device__ __align__(16) __half g_WkT[(size_t)H_ * DK_ * D_];
__device__ __align__(16) __half g_WvT[(size_t)H_ * DK_ * D_];
__device__ __align__(16) __half g_WoT[(size_t)D_ * (A_ * DK_)];

// ---------------- helpers -----------------------------------------------------
static __device__ __forceinline__ void mma16816(float* c, const uint32_t* a,
                                                const uint32_t* b) {
    asm volatile(
        "mma.sync.aligned.m16n8k16.row.col.f32.f16.f16.f32 "
        "{%0,%1,%2,%3}, {%4,%5,%6,%7}, {%8,%9}, {%0,%1,%2,%3};"
        : "+f"(c[0]), "+f"(c[1]), "+f"(c[2]), "+f"(c[3])
        : "r"(a[0]), "r"(a[1]), "r"(a[2]), "r"(a[3]), "r"(b[0]), "r"(b[1]));
}
static __device__ __forceinline__ uint32_t smem_u32(const void* p) {
    uint32_t a;
    asm("{ .reg .u64 t; cvta.to.shared.u64 t, %1; cvt.u32.u64 %0, t; }"
        : "=r"(a) : "l"(p));
    return a;
}
static __device__ __forceinline__ uint32_t h2pack(float a, float b) {
    __half2 h = __floats2half2_rn(a, b);
    return *(uint32_t*)&h;
}
#define LDSM4(r0, r1, r2, r3, a) \
    asm volatile("ldmatrix.sync.aligned.m8n8.x4.shared.b16 {%0,%1,%2,%3}, [%4];" \
        : "=r"(r0), "=r"(r1), "=r"(r2), "=r"(r3) : "r"(a))
#define CP16(dst, src) \
    asm volatile("cp.async.cg.shared.global [%0], [%1], 16;" :: "r"(dst), "l"(src))
#define CP_COMMIT() asm volatile("cp.async.commit_group;" ::: "memory")
#define CP_WAIT(n)  asm volatile("cp.async.wait_group %0;" :: "n"(n) : "memory")

// ---------------- 1) fused mean + fp16 copy of x ------------------------------
__global__ void mean_copy_kernel(const float* __restrict__ x) {
    int b = blockIdx.y;
    int d = blockIdx.x * 256 + threadIdx.x;
    const float* xp = x + (size_t)b * S_ * D_ + d;
    __half* hp = g_xh + (size_t)b * S_ * D_ + d;
    float s = 0.f;
    #pragma unroll 4
    for (int t = 0; t < S_; ++t) {
        float v = xp[(size_t)t * D_];
        s += v;
        hp[(size_t)t * D_] = __float2half_rn(v);
    }
    g_xmean[b * D_ + d] = s * (1.0f / (float)S_);
}

// ---------------- 2) router ---------------------------------------------------
__global__ void router_kernel(const float* __restrict__ Wr,
                              const float* __restrict__ br) {
    int b = blockIdx.x;
    __shared__ float red[128][H_];
    int tid = threadIdx.x;
    float acc[H_];
    #pragma unroll
    for (int h = 0; h < H_; ++h) acc[h] = 0.f;
    for (int d = tid; d < D_; d += 128) {
        float xv = g_xmean[b * D_ + d];
        #pragma unroll
        for (int h = 0; h < H_; ++h) acc[h] += xv * Wr[d * H_ + h];
    }
    #pragma unroll
    for (int h = 0; h < H_; ++h) red[tid][h] = acc[h];
    __syncthreads();
    if (tid == 0) {
        float logit[H_];
        for (int h = 0; h < H_; ++h) {
            float s = 0.f;
            for (int t = 0; t < 128; ++t) s += red[t][h];
            logit[h] = s + br[h];
        }
        float mx = logit[0];
        for (int h = 1; h < H_; ++h) mx = fmaxf(mx, logit[h]);
        float dist[H_], sum = 0.f;
        for (int h = 0; h < H_; ++h) { dist[h] = expf(logit[h] - mx); sum += dist[h]; }
        for (int h = 0; h < H_; ++h) dist[h] /= sum;
        bool used[H_];
        for (int h = 0; h < H_; ++h) used[h] = false;
        int idxs[A_]; float vals[A_];
        for (int a = 0; a < A_; ++a) {
            int best = -1; float bv = -1.f;
            for (int h = 0; h < H_; ++h)
                if (!used[h] && dist[h] > bv) { bv = dist[h]; best = h; }
            used[best] = true; idxs[a] = best; vals[a] = bv;
        }
        float denom = (float)(H_ - A_);
        float ev[A_];
        for (int a = 0; a < A_; ++a) { ev[a] = expf(vals[a]); denom += ev[a]; }
        for (int a = 0; a < A_; ++a) {
            g_idx [b * A_ + a] = idxs[a];
            g_gate[b * A_ + a] = ev[a] / denom;
        }
    }
}

// ---------------- weight transposes (emit fp16) -------------------------------
__global__ void transpose_heads(const float* __restrict__ Wq,
                                const float* __restrict__ Wk,
                                const float* __restrict__ Wv) {
    __shared__ float t[32][33];
    int zb = blockIdx.z;
    int mat = zb >> 4, h = zb & 15;
    const float* W = (mat == 0) ? Wq : (mat == 1) ? Wk : Wv;
    __half*      O = (mat == 0) ? g_WqT : (mat == 1) ? g_WkT : g_WvT;
    int k0 = blockIdx.x * 32, n0 = blockIdx.y * 32;
    int tx = threadIdx.x, ty = threadIdx.y;
    const float* Wh = W + (size_t)h * D_ * DK_;
    __half*      Oh = O + (size_t)h * DK_ * D_;
    #pragma unroll
    for (int i = 0; i < 4; ++i)
        t[ty + 8 * i][tx] = Wh[(size_t)(k0 + ty + 8 * i) * DK_ + n0 + tx];
    __syncthreads();
    #pragma unroll
    for (int i = 0; i < 4; ++i)
        Oh[(size_t)(n0 + ty + 8 * i) * D_ + k0 + tx] = __float2half_rn(t[tx][ty + 8 * i]);
}

__global__ void transpose_wo(const float* __restrict__ Wo) {
    __shared__ float t[32][33];
    int k0 = blockIdx.x * 32, n0 = blockIdx.y * 32;
    int tx = threadIdx.x, ty = threadIdx.y;
    #pragma unroll
    for (int i = 0; i < 4; ++i)
        t[ty + 8 * i][tx] = Wo[(size_t)(k0 + ty + 8 * i) * D_ + n0 + tx];
    __syncthreads();
    #pragma unroll
    for (int i = 0; i < 4; ++i)
        g_WoT[(size_t)(n0 + ty + 8 * i) * (A_ * DK_) + k0 + tx] =
            __float2half_rn(t[tx][ty + 8 * i]);
}

// == fp16 GEMM, 8 warps / 32x64 warp tiles, single-barrier double buffer ========
#define PITCH_H 72
#define GEMM_SMEM_BYTES (4 * 128 * PITCH_H * 2)   // 73728

// EPI: 0 plain fp32 (+bias), 1 Q ((acc+bias)*sc -> fp16),
//      2 V transposed (+bias -> fp16), 3 K (+bias -> fp16)
template<int EPI>
static __device__ __forceinline__ void gemm128_h(
    const __half* __restrict__ A, int lda,
    const __half* __restrict__ Bt, int ldb,
    const float* __restrict__ bias,
    void* __restrict__ Cv, int ldc, int K, float sc)
{
    extern __shared__ __half shh[];
    const uint32_t base = smem_u32(shh);
    const uint32_t bufA[2] = { base,                         base + 128 * PITCH_H * 2 };
    const uint32_t bufB[2] = { base + 2 * 128 * PITCH_H * 2, base + 3 * 128 * PITCH_H * 2 };

    const int tid  = threadIdx.x;          // 256 threads
    const int lane = tid & 31;
    const int wid  = tid >> 5;
    const int wm   = wid & 3;
    const int wn   = wid >> 2;
    const int g    = lane >> 2;
    const int tig  = lane & 3;

    const int row = tid >> 1;
    const int hh  = (tid & 1);
    const __half* Ap = A  + (size_t)row * lda + hh * 32;
    const __half* Bp = Bt + (size_t)row * ldb + hh * 32;
    uint32_t sA[2], sB[2];
    sA[0] = bufA[0] + row * (PITCH_H * 2) + hh * 64;
    sA[1] = bufA[1] + row * (PITCH_H * 2) + hh * 64;
    sB[0] = bufB[0] + row * (PITCH_H * 2) + hh * 64;
    sB[1] = bufB[1] + row * (PITCH_H * 2) + hh * 64;

    const int arow = lane & 15;
    const int aco  = (lane >> 4) * 16;
    const int brow = ((lane >> 4) & 1) * 8 + (lane & 7);
    const int bco  = ((lane >> 3) & 1) * 16;
    uint32_t aAddr[2][2], bAddr[2][4];
    #pragma unroll
    for (int buf = 0; buf < 2; ++buf) {
        #pragma unroll
        for (int mi = 0; mi < 2; ++mi)
            aAddr[buf][mi] = bufA[buf] + (wm * 32 + mi * 16 + arow) * (PITCH_H * 2) + aco;
        #pragma unroll
        for (int p = 0; p < 4; ++p)
            bAddr[buf][p] = bufB[buf] + (wn * 64 + p * 16 + brow) * (PITCH_H * 2) + bco;
    }

    const int KIT = K >> 6;

    // prologue: stage 0
    #pragma unroll
    for (int j = 0; j < 4; ++j) {
        CP16(sA[0] + j * 16, Ap + j * 8);
        CP16(sB[0] + j * 16, Bp + j * 8);
    }
    CP_COMMIT();

    float acc[2][8][4];
    #pragma unroll
    for (int mi = 0; mi < 2; ++mi)
        #pragma unroll
        for (int ni = 0; ni < 8; ++ni)
            #pragma unroll
            for (int r = 0; r < 4; ++r) acc[mi][ni][r] = 0.f;

    for (int it = 0; it < KIT; ++it) {
        CP_WAIT(0);            // stage it resident
        __syncthreads();       // all warps done with iter it-1 (frees buf (it+1)&1)
        if (it + 1 < KIT) {    // prefetch stage it+1 under compute of stage it
            const __half* An = Ap + (size_t)(it + 1) * 64;
            const __half* Bn = Bp + (size_t)(it + 1) * 64;
            int nb = (it + 1) & 1;
            #pragma unroll
            for (int j = 0; j < 4; ++j) {
                CP16(sA[nb] + j * 16, An + j * 8);
                CP16(sB[nb] + j * 16, Bn + j * 8);
            }
            CP_COMMIT();
        }

        const int buf = it & 1;
        #pragma unroll
        for (int ks = 0; ks < 4; ++ks) {
            uint32_t a0[4], a1[4];
            LDSM4(a0[0], a0[1], a0[2], a0[3], aAddr[buf][0] + ks * 32);
            LDSM4(a1[0], a1[1], a1[2], a1[3], aAddr[buf][1] + ks * 32);
            #pragma unroll
            for (int p = 0; p < 4; ++p) {
                uint32_t bb[4];
                LDSM4(bb[0], bb[1], bb[2], bb[3], bAddr[buf][p] + ks * 32);
                mma16816(acc[0][2 * p],     a0, bb);
                mma16816(acc[1][2 * p],     a1, bb);
                mma16816(acc[0][2 * p + 1], a0, bb + 2);
                mma16816(acc[1][2 * p + 1], a1, bb + 2);
            }
        }
    }

    #pragma unroll
    for (int mi = 0; mi < 2; ++mi) {
        int r0 = wm * 32 + mi * 16 + g;
        #pragma unroll
        for (int ni = 0; ni < 8; ++ni) {
            int c = wn * 64 + ni * 8 + 2 * tig;
            float b0 = __ldg(bias + c), b1 = __ldg(bias + c + 1);
            float v0 = acc[mi][ni][0] + b0, v1 = acc[mi][ni][1] + b1;
            float v2 = acc[mi][ni][2] + b0, v3 = acc[mi][ni][3] + b1;
            if (EPI == 0) {
                float* C = (float*)Cv;
                *(float2*)&C[(size_t)r0 * ldc + c]       = make_float2(v0, v1);
                *(float2*)&C[(size_t)(r0 + 8) * ldc + c] = make_float2(v2, v3);
            } else if (EPI == 1) {
                __half* C = (__half*)Cv;
                *(__half2*)&C[(size_t)r0 * ldc + c]       = __floats2half2_rn(v0 * sc, v1 * sc);
                *(__half2*)&C[(size_t)(r0 + 8) * ldc + c] = __floats2half2_rn(v2 * sc, v3 * sc);
            } else if (EPI == 2) {
                __half* C = (__half*)Cv;
                C[(size_t)c * ldc + r0]           = __float2half_rn(v0);
                C[(size_t)(c + 1) * ldc + r0]     = __float2half_rn(v1);
                C[(size_t)c * ldc + r0 + 8]       = __float2half_rn(v2);
                C[(size_t)(c + 1) * ldc + r0 + 8] = __float2half_rn(v3);
            } else {
                __half* C = (__half*)Cv;
                *(__half2*)&C[(size_t)r0 * ldc + c]       = __floats2half2_rn(v0, v1);
                *(__half2*)&C[(size_t)(r0 + 8) * ldc + c] = __floats2half2_rn(v2, v3);
            }
        }
    }
}

// ---------------- 3) gathered QKV projections ---------------------------------
__global__ void __launch_bounds__(256, 2) qkv_tc(const float* __restrict__ bq,
                                                 const float* __restrict__ bk,
                                                 const float* __restrict__ bv) {
    int z = blockIdx.z;
    int b = z >> 2;
    int h = g_idx[z];
    const __half* Atile = g_xh + (size_t)b * S_ * D_ + (size_t)blockIdx.x * 128 * D_;
    const float sc = 0.08838834764831845f;
    if (blockIdx.y == 0) {
        __half* C = g_Q + (size_t)z * S_ * DK_ + (size_t)blockIdx.x * 128 * DK_;
        gemm128_h<1>(Atile, D_, g_WqT + (size_t)h * DK_ * D_, D_,
                     bq + h * DK_, C, DK_, D_, sc);
    } else if (blockIdx.y == 1) {
        __half* C = g_K + (size_t)z * S_ * DK_ + (size_t)blockIdx.x * 128 * DK_;
        gemm128_h<3>(Atile, D_, g_WkT + (size_t)h * DK_ * D_, D_,
                     bk + h * DK_, C, DK_, D_, 1.f);
    } else {
        __half* C = g_Vt + (size_t)z * DK_ * S_ + blockIdx.x * 128;
        gemm128_h<2>(Atile, D_, g_WvT + (size_t)h * DK_ * D_, D_,
                     bv + h * DK_, C, S_, D_, 1.f);
    }
}

// ---------------- 4) fp16 flash attention (occ 2, reg-P, dbl-buf K+V) ---------
// smem halves: Q[128*136]@0, K0@17408, K1@26112, V0[128*72]@34816, V1@44032
#define FL_Q   0
#define FL_K0  17408
#define FL_K1  26112
#define FL_V0  34816
#define FL_V1  44032
#define FL_SMEM_BYTES ((44032 + 128 * 72) * 2)   // 106496

__global__ void __launch_bounds__(256, 2) flash_tc() {
    extern __shared__ __half fsh[];
    const int z = blockIdx.y, b = z >> 2, a = z & 3;
    const __half* Qg = g_Q + (size_t)z * S_ * DK_;
    const __half* Kg = g_K + (size_t)z * S_ * DK_;
    const __half* Vg = g_Vt + (size_t)z * DK_ * S_;
    const int tid = threadIdx.x, lane = tid & 31, w = tid >> 5;
    const int g = lane >> 2, tig = lane & 3;
    const int m0 = w * 16;
    const int qrow0 = blockIdx.x * 128;
    const uint32_t fsb = smem_u32(fsh);

    // cp.async mappings (double-buffered K and V)
    const int krow = tid >> 2;
    uint32_t sK[2];
    sK[0] = fsb + (FL_K0 + krow * 136) * 2 + (tid & 3) * 64;
    sK[1] = fsb + (FL_K1 + krow * 136) * 2 + (tid & 3) * 64;
    const __half* Kp = Kg + (size_t)krow * DK_ + (tid & 3) * 32;
    const int vrow = tid >> 1;
    uint32_t sV[2];
    sV[0] = fsb + (FL_V0 + vrow * 72) * 2 + (tid & 1) * 64;
    sV[1] = fsb + (FL_V1 + vrow * 72) * 2 + (tid & 1) * 64;
    const __half* Vp = Vg + (size_t)vrow * S_ + (tid & 1) * 32;

    // ldmatrix lane addressing
    const int arow = lane & 15;
    const int aco  = (lane >> 4) * 16;
    const int brow = ((lane >> 4) & 1) * 8 + (lane & 7);
    const int bco  = ((lane >> 3) & 1) * 16;
    const uint32_t qAddr = fsb + (FL_Q + (m0 + arow) * 136) * 2 + aco;
    uint32_t kAddr[2][4], vAddr[2][8];
    #pragma unroll
    for (int p = 0; p < 4; ++p) {
        kAddr[0][p] = fsb + (FL_K0 + (p * 16 + brow) * 136) * 2 + bco;
        kAddr[1][p] = fsb + (FL_K1 + (p * 16 + brow) * 136) * 2 + bco;
    }
    #pragma unroll
    for (int p = 0; p < 8; ++p) {
        vAddr[0][p] = fsb + (FL_V0 + (p * 16 + brow) * 72) * 2 + bco;
        vAddr[1][p] = fsb + (FL_V1 + (p * 16 + brow) * 72) * 2 + bco;
    }

    // prologue: K(0) + V(0) as one group
    #pragma unroll
    for (int j = 0; j < 4; ++j) CP16(sK[0] + j * 16, Kp + j * 8);
    #pragma unroll
    for (int j = 0; j < 4; ++j) CP16(sV[0] + j * 16, Vp + j * 8);
    CP_COMMIT();

    // Q fill
    #pragma unroll
    for (int l = 0; l < 8; ++l) {
        int chunk = tid + l * 256;
        int r = chunk >> 4, c = (chunk & 15) * 8;
        *(uint4*)&fsh[FL_Q + r * 136 + c] =
            *(const uint4*)(Qg + (size_t)(qrow0 + r) * DK_ + c);
    }

    float o[16][4];
    #pragma unroll
    for (int ni = 0; ni < 16; ++ni)
        #pragma unroll
        for (int r = 0; r < 4; ++r) o[ni][r] = 0.f;
    float mr0 = -1e30f, mr1 = -1e30f, l0 = 0.f, l1 = 0.f;

    for (int kt = 0; kt < S_ / 64; ++kt) {
        CP_WAIT(0);            // K(kt), V(kt) resident
        __syncthreads();       // all warps finished iter kt-1 (frees buf (kt+1)&1)
        if (kt + 1 < S_ / 64) {
            const __half* Kn = Kp + (size_t)(kt + 1) * 64 * DK_;
            const __half* Vn = Vp + (size_t)(kt + 1) * 64;
            const int nb = (kt + 1) & 1;
            #pragma unroll
            for (int j = 0; j < 4; ++j) CP16(sK[nb] + j * 16, Kn + j * 8);
            #pragma unroll
            for (int j = 0; j < 4; ++j) CP16(sV[nb] + j * 16, Vn + j * 8);
            CP_COMMIT();
        }

        // ---- S = Q K^T (Q fragments reloaded per tile: fits 128-reg cap) ----
        const int kb = kt & 1;
        float sacc[8][4];
        #pragma unroll
        for (int ni = 0; ni < 8; ++ni)
            #pragma unroll
            for (int r = 0; r < 4; ++r) sacc[ni][r] = 0.f;

        #pragma unroll
        for (int ks = 0; ks < 8; ++ks) {
            uint32_t aq[4];
            LDSM4(aq[0], aq[1], aq[2], aq[3], qAddr + ks * 32);
            #pragma unroll
            for (int p = 0; p < 4; ++p) {
                uint32_t bb[4];
                LDSM4(bb[0], bb[1], bb[2], bb[3], kAddr[kb][p] + ks * 32);
                mma16816(sacc[2 * p],     aq, bb);
                mma16816(sacc[2 * p + 1], aq, bb + 2);
            }
        }

        // ---- online softmax ----
        float mt0 = -1e30f, mt1 = -1e30f;
        #pragma unroll
        for (int ni = 0; ni < 8; ++ni) {
            mt0 = fmaxf(mt0, fmaxf(sacc[ni][0], sacc[ni][1]));
            mt1 = fmaxf(mt1, fmaxf(sacc[ni][2], sacc[ni][3]));
        }
        mt0 = fmaxf(mt0, __shfl_xor_sync(0xffffffffu, mt0, 1));
        mt0 = fmaxf(mt0, __shfl_xor_sync(0xffffffffu, mt0, 2));
        mt1 = fmaxf(mt1, __shfl_xor_sync(0xffffffffu, mt1, 1));
        mt1 = fmaxf(mt1, __shfl_xor_sync(0xffffffffu, mt1, 2));

        float mn0 = fmaxf(mr0, mt0), mn1 = fmaxf(mr1, mt1);
        float al0 = __expf(mr0 - mn0), al1 = __expf(mr1 - mn1);
        float ls0 = 0.f, ls1 = 0.f;
        #pragma unroll
        for (int ni = 0; ni < 8; ++ni) {
            sacc[ni][0] = __expf(sacc[ni][0] - mn0);
            sacc[ni][1] = __expf(sacc[ni][1] - mn0);
            sacc[ni][2] = __expf(sacc[ni][2] - mn1);
            sacc[ni][3] = __expf(sacc[ni][3] - mn1);
            ls0 += sacc[ni][0] + sacc[ni][1];
            ls1 += sacc[ni][2] + sacc[ni][3];
        }
        ls0 += __shfl_xor_sync(0xffffffffu, ls0, 1);
        ls0 += __shfl_xor_sync(0xffffffffu, ls0, 2);
        ls1 += __shfl_xor_sync(0xffffffffu, ls1, 1);
        ls1 += __shfl_xor_sync(0xffffffffu, ls1, 2);

        l0 = l0 * al0 + ls0;  mr0 = mn0;
        l1 = l1 * al1 + ls1;  mr1 = mn1;

        #pragma unroll
        for (int ni = 0; ni < 16; ++ni) {
            o[ni][0] *= al0; o[ni][1] *= al0;
            o[ni][2] *= al1; o[ni][3] *= al1;
        }

        // ---- P: C-fragment -> A-fragment in registers ----
        uint32_t pf[4][4];
        #pragma unroll
        for (int ks = 0; ks < 4; ++ks) {
            pf[ks][0] = h2pack(sacc[2 * ks][0],     sacc[2 * ks][1]);
            pf[ks][1] = h2pack(sacc[2 * ks][2],     sacc[2 * ks][3]);
            pf[ks][2] = h2pack(sacc[2 * ks + 1][0], sacc[2 * ks + 1][1]);
            pf[ks][3] = h2pack(sacc[2 * ks + 1][2], sacc[2 * ks + 1][3]);
        }

        // ---- O += P V ----
        #pragma unroll
        for (int ks = 0; ks < 4; ++ks) {
            #pragma unroll
            for (int p = 0; p < 8; ++p) {
                uint32_t bb[4];
                LDSM4(bb[0], bb[1], bb[2], bb[3], vAddr[kb][p] + ks * 32);
                mma16816(o[2 * p],     pf[ks], bb);
                mma16816(o[2 * p + 1], pf[ks], bb + 2);
            }
        }
    }

    // ---- epilogue: normalize, gate, concat (fp16) ----
    float gate = g_gate[z];
    float inv0 = gate / l0, inv1 = gate / l1;
    int r0 = qrow0 + m0 + g, r1 = r0 + 8;
    __half* ob0 = g_cat + ((size_t)b * S_ + r0) * (A_ * DK_) + a * DK_;
    __half* ob1 = g_cat + ((size_t)b * S_ + r1) * (A_ * DK_) + a * DK_;
    #pragma unroll
    for (int ni = 0; ni < 16; ++ni) {
        int c = ni * 8 + 2 * tig;
        *(__half2*)&ob0[c] = __floats2half2_rn(o[ni][0] * inv0, o[ni][1] * inv0);
        *(__half2*)&ob1[c] = __floats2half2_rn(o[ni][2] * inv1, o[ni][3] * inv1);
    }
}

// ---------------- 5) output projection -----------------------------------------
__global__ void __launch_bounds__(256, 2) outproj_tc(const float* __restrict__ bo,
                                                     float* __restrict__ out) {
    const __half* Atile = g_cat + (size_t)blockIdx.x * 128 * (A_ * DK_);
    const __half* Bt = g_WoT + (size_t)blockIdx.y * 128 * (A_ * DK_);
    float* C = out + (size_t)blockIdx.x * 128 * D_ + blockIdx.y * 128;
    gemm128_h<0>(Atile, A_ * DK_, Bt, A_ * DK_, bo + blockIdx.y * 128,
                 C, D_, A_ * DK_, 1.f);
}

// ---------------- launch --------------------------------------------------------
extern "C" void kernel_launch(void* const* d_in, const int* in_sizes, int n_in,
                              void* d_out, int out_size) {
    const float* x  = (const float*)d_in[0];
    const float* Wq = (const float*)d_in[1];
    const float* bq = (const float*)d_in[2];
    const float* Wk = (const float*)d_in[3];
    const float* bk = (const float*)d_in[4];
    const float* Wv = (const float*)d_in[5];
    const float* bv = (const float*)d_in[6];
    const float* Wr = (const float*)d_in[7];
    const float* br = (const float*)d_in[8];
    const float* Wo = (const float*)d_in[9];
    const float* bo = (const float*)d_in[10];
    float* out = (float*)d_out;

    cudaFuncSetAttribute(flash_tc, cudaFuncAttributeMaxDynamicSharedMemorySize,
                         FL_SMEM_BYTES);
    cudaFuncSetAttribute(qkv_tc, cudaFuncAttributeMaxDynamicSharedMemorySize,
                         GEMM_SMEM_BYTES);
    cudaFuncSetAttribute(outproj_tc, cudaFuncAttributeMaxDynamicSharedMemorySize,
                         GEMM_SMEM_BYTES);

    mean_copy_kernel<<<dim3(D_ / 256, B_), 256>>>(x);
    router_kernel   <<<B_, 128>>>(Wr, br);
    transpose_heads <<<dim3(D_ / 32, DK_ / 32, 3 * H_), dim3(32, 8)>>>(Wq, Wk, Wv);
    transpose_wo    <<<dim3((A_ * DK_) / 32, D_ / 32), dim3(32, 8)>>>(Wo);
    qkv_tc          <<<dim3(S_ / 128, 3, B_ * A_), 256, GEMM_SMEM_BYTES>>>(bq, bk, bv);
    flash_tc        <<<dim3(S_ / 128, B_ * A_), 256, FL_SMEM_BYTES>>>();
    outproj_tc      <<<dim3((B_ * S_) / 128, D_ / 128), 256, GEMM_SMEM_BYTES>>>(bo, out);
}